// round 11
// baseline (speedup 1.0000x reference)
#include <cuda_runtime.h>
#include <math.h>
#include <stdint.h>

#define NN 512
#define EMB 64
#define HID 128
#define G4 512   // 4*HID
#define IN2 128  // 2*EMB

#define SMEM_D 48           // Wp rows resident in SMEM
#define RREM (HID - SMEM_D) // 80 rows in registers (160 x 64-bit halves)
// dynamic smem floats: sWp + double-buffered h dup quads
#define LSTM_SMEM_FLOATS (SMEM_D * G4 + 2 * HID * 8)
#define LSTM_SMEM_BYTES (LSTM_SMEM_FLOATS * 4)

// ---- scratch (device globals; no allocations allowed) ----
__device__ float g_input_feat[NN * IN2];   // [node][128]
__device__ float g_ihc4[NN * G4];          // [node][d][(i,f,g,o)]
__device__ int   g_orders[NN * NN];        // [start][step]
__device__ float g_Wp[HID * G4];           // [d'][d][(i,f,g,o)]
__device__ float g_embed[NN * HID];        // mean LSTM output per sequence
__device__ float g_logits[4 * NN];

// packed fp32x2 FMA (Blackwell): acc = a*b + acc, lanewise IEEE fp32
#define FFMA2(acc, a, b) \
    asm("fma.rn.f32x2 %0, %1, %2, %0;" : "+l"(acc) : "l"(a), "l"(b))

// ---------------- Threefry2x32 (JAX-compatible) ----------------
__device__ __forceinline__ uint32_t rotl32(uint32_t x, int d) {
    return (x << d) | (x >> (32 - d));
}

__device__ __forceinline__ void threefry(uint32_t k0, uint32_t k1,
                                         uint32_t& x0, uint32_t& x1) {
    uint32_t ks2 = k0 ^ k1 ^ 0x1BD11BDAu;
    x0 += k0; x1 += k1;
    x0 += x1; x1 = rotl32(x1, 13); x1 ^= x0;
    x0 += x1; x1 = rotl32(x1, 15); x1 ^= x0;
    x0 += x1; x1 = rotl32(x1, 26); x1 ^= x0;
    x0 += x1; x1 = rotl32(x1, 6);  x1 ^= x0;
    x0 += k1; x1 += ks2 + 1u;
    x0 += x1; x1 = rotl32(x1, 17); x1 ^= x0;
    x0 += x1; x1 = rotl32(x1, 29); x1 ^= x0;
    x0 += x1; x1 = rotl32(x1, 16); x1 ^= x0;
    x0 += x1; x1 = rotl32(x1, 24); x1 ^= x0;
    x0 += ks2; x1 += k0 + 2u;
    x0 += x1; x1 = rotl32(x1, 13); x1 ^= x0;
    x0 += x1; x1 = rotl32(x1, 15); x1 ^= x0;
    x0 += x1; x1 = rotl32(x1, 26); x1 ^= x0;
    x0 += x1; x1 = rotl32(x1, 6);  x1 ^= x0;
    x0 += k0; x1 += k1 + 3u;
    x0 += x1; x1 = rotl32(x1, 17); x1 ^= x0;
    x0 += x1; x1 = rotl32(x1, 29); x1 ^= x0;
    x0 += x1; x1 = rotl32(x1, 16); x1 ^= x0;
    x0 += x1; x1 = rotl32(x1, 24); x1 ^= x0;
    x0 += k1; x1 += ks2 + 4u;
    x0 += x1; x1 = rotl32(x1, 13); x1 ^= x0;
    x0 += x1; x1 = rotl32(x1, 15); x1 ^= x0;
    x0 += x1; x1 = rotl32(x1, 26); x1 ^= x0;
    x0 += x1; x1 = rotl32(x1, 6);  x1 ^= x0;
    x0 += ks2; x1 += k0 + 5u;
}

// fast activations (err ~1e-6; recurrence is contractive)
__device__ __forceinline__ float fsig(float x) {
    return __fdividef(1.0f, 1.0f + __expf(-x));
}
__device__ __forceinline__ float ftanh(float x) {
    return __fdividef(2.0f, 1.0f + __expf(-2.0f * x)) - 1.0f;
}
__device__ __forceinline__ float sigf(float x) {  // accurate (non-LSTM paths)
    return 1.0f / (1.0f + expf(-x));
}

// ---------------- Kernel A: node_feat / neigh_feat + W_hh repack ----------
__global__ void k_embed(const int* __restrict__ tags,
                        const float* __restrict__ adj,
                        const float* __restrict__ W_emb,
                        const float* __restrict__ b_emb,
                        const float* __restrict__ W_hh) {
    int i = blockIdx.x;
    int dd = threadIdx.x;  // 64
    __shared__ int stags[NN];
    for (int j = dd; j < NN; j += 64) stags[j] = tags[j];
    __syncthreads();
    float nf = W_emb[stags[i] * EMB + dd] + b_emb[dd];
    float acc = 0.f;
    const float* arow = adj + (size_t)i * NN;
    for (int j = 0; j < NN; j++) {
        if (arow[j] > 0.5f) acc += W_emb[stags[j] * EMB + dd];
    }
    g_input_feat[i * IN2 + dd] = nf;
    g_input_feat[i * IN2 + EMB + dd] = acc + b_emb[dd];

    // fused W repack: g_Wp[d'*512 + d*4 + g] = W_hh[(g*128+d)*128 + d']
    int e0 = (i * 64 + dd) * 2;
#pragma unroll
    for (int c = 0; c < 2; c++) {
        int e = e0 + c;
        int dp = e >> 9;
        int rem = e & 511;
        int dcol = rem >> 2;
        int g = rem & 3;
        g_Wp[e] = W_hh[(g * 128 + dcol) * 128 + dp];
    }
}

// ---------------- Kernel C: per-node input-gate contribution --------------
// stores gate-interleaved: g_ihc4[node][d][(i,f,g,o)]
__global__ void k_ihc(const float* __restrict__ W_ih,
                      const float* __restrict__ b_ih,
                      const float* __restrict__ b_hh) {
    int node = blockIdx.x;
    int j = threadIdx.x;  // 512; j = g*128 + d
    __shared__ float sx[IN2];
    if (j < IN2) sx[j] = g_input_feat[node * IN2 + j];
    __syncthreads();
    const float* wr = W_ih + j * IN2;
    float acc = 0.f;
#pragma unroll 8
    for (int d = 0; d < IN2; d++) acc += sx[d] * wr[d];
    int g = j >> 7, dcol = j & 127;
    g_ihc4[node * G4 + dcol * 4 + g] = acc + b_ih[j] + b_hh[j];
}

// ---------------- Kernel D: greedy noisy random-walk orderings ------------
// Partitionable threefry (bit-exact, verified R5-R9) + exact candidate filter
// (noise in [0.01,0.1) => only i with adj[cur,i] >= max-0.09001 can win).
// v4: no smem atomics, no serial tid0 scans — per-warp STS + all-thread local
// reduce of 8 values; warp-count prefix instead of atomicAdd; reg-resident mask.
__device__ __forceinline__ float walk_noise1(uint32_t f1, uint32_t f2, int i) {
    const float scale = 0.1f - 0.01f;
    uint32_t a = 0u, b = (uint32_t)i;
    threefry(f1, f2, a, b);
    uint32_t bits = a ^ b;
    float u = __uint_as_float((bits >> 9) | 0x3f800000u) - 1.0f;
    return fmaxf(0.01f, __fadd_rn(__fmul_rn(u, scale), 0.01f));
}

__global__ void __launch_bounds__(256) k_orders(const float* __restrict__ adj) {
    int s = blockIdx.x;
    int tid = threadIdx.x;  // 256
    int lane = tid & 31, warp = tid >> 5;
    __shared__ uint32_t fi1[NN], fi2[NN];
    __shared__ float wmax[8];
    __shared__ int wcnt[8];
    __shared__ unsigned long long wred[8];
    __shared__ short slist[NN];

    uint32_t k1 = 0u, k2 = (uint32_t)s;
    threefry(0u, 42u, k1, k2);  // split(key(42), 512)[s]
#pragma unroll
    for (int c = 0; c < 2; c++) {
        int t = tid + c * 256;
        uint32_t f1 = 0u, f2 = (uint32_t)t;
        threefry(k1, k2, f1, f2);
        fi1[t] = f1; fi2[t] = f2;
    }
    if (tid == 0) g_orders[s * NN] = s;
    bool mask0 = (tid != s);
    bool mask1 = (tid + 256 != s);
    int cur = s;
    __syncthreads();

    for (int t = 0; t < NN - 1; t++) {
        const float* arow = adj + (size_t)cur * NN;
        float a0 = arow[tid], a1 = arow[tid + 256];

        // phase 1: masked max
        float mx = fmaxf(mask0 ? a0 : -1.f, mask1 ? a1 : -1.f);
#pragma unroll
        for (int off = 16; off > 0; off >>= 1)
            mx = fmaxf(mx, __shfl_xor_sync(0xffffffffu, mx, off));
        if (lane == 0) wmax[warp] = mx;
        __syncthreads();  // s1

        float thr = wmax[0];
#pragma unroll
        for (int w = 1; w < 8; w++) thr = fmaxf(thr, wmax[w]);
        float thr2 = thr - 0.09001f;

        // phase 2: ballot + per-warp counts
        bool c0 = mask0 && (a0 >= thr2);
        bool c1 = mask1 && (a1 >= thr2);
        unsigned bal0 = __ballot_sync(0xffffffffu, c0);
        unsigned bal1 = __ballot_sync(0xffffffffu, c1);
        if (lane == 0) wcnt[warp] = __popc(bal0) + __popc(bal1);
        __syncthreads();  // s2

        int basew = 0, nc = 0;
#pragma unroll
        for (int w = 0; w < 8; w++) {
            int cw = wcnt[w];
            if (w < warp) basew += cw;
            nc += cw;
        }
        unsigned lmask = (1u << lane) - 1u;
        if (c0) slist[basew + __popc(bal0 & lmask)] = (short)tid;
        if (c1) slist[basew + __popc(bal0) + __popc(bal1 & lmask)] =
            (short)(tid + 256);
        __syncthreads();  // s3

        // phase 3: ciphers only for candidates
        uint32_t f1 = fi1[t], f2 = fi2[t];
        unsigned long long key = 0ull;
        if (tid < nc) {
            int i = slist[tid];
            float v = arow[i] + walk_noise1(f1, f2, i);
            key = (((unsigned long long)__float_as_uint(v)) << 32) |
                  (unsigned long long)(unsigned)(NN - 1 - i);
        }
        if (tid + 256 < nc) {
            int i = slist[tid + 256];
            float v = arow[i] + walk_noise1(f1, f2, i);
            unsigned long long kk =
                (((unsigned long long)__float_as_uint(v)) << 32) |
                (unsigned long long)(unsigned)(NN - 1 - i);
            if (kk > key) key = kk;
        }
#pragma unroll
        for (int off = 16; off > 0; off >>= 1) {
            unsigned long long o = __shfl_xor_sync(0xffffffffu, key, off);
            if (o > key) key = o;
        }
        if (lane == 0) wred[warp] = key;
        __syncthreads();  // s4

        unsigned long long best = wred[0];
#pragma unroll
        for (int w = 1; w < 8; w++) if (wred[w] > best) best = wred[w];
        int nxt = (NN - 1) - (int)(unsigned)(best & 0xffffffffu);
        if (nxt == tid) mask0 = false;
        if (nxt == tid + 256) mask1 = false;
        if (tid == 0) g_orders[s * NN + t + 1] = nxt;
        cur = nxt;
        // no trailing sync: next writes (wmax) are separated from this step's
        // reads by next s1..; slist next write is after next s2 (>= 2 syncs).
    }
}

// ---------------- Kernel E: LSTM, cell-owned, ONE barrier per step --------
// Thread t owns cells (b0,d) and (b1,d), d = t&127, {b0,b1} = {0,1} or {2,3}.
// Its 4 accs are packed (i,f)/(g,o) pairs, so gates never cross threads:
// GEMV -> activations -> h store, one __syncthreads per step, h double-buffered.
__global__ void __launch_bounds__(256) k_lstm() {
    extern __shared__ float smem[];
    float* sWp = smem;                  // [SMEM_D][512] = [d'][d][(i,f,g,o)]
    float* sh2 = smem + SMEM_D * G4;    // [2][128][8] dup quads (h,h,h,h)

    int bb = blockIdx.x;     // 0..127
    int tid = threadIdx.x;   // 0..255
    int base = bb * 4;
    int d = tid & 127;
    int bg = tid >> 7;       // 0 or 1
    int b0 = bg * 2, b1 = bg * 2 + 1;

    // stage sWp rows
    {
        const float4* src = (const float4*)g_Wp;
        float4* dst = (float4*)sWp;
        for (int i = tid; i < SMEM_D * G4 / 4; i += 256) dst[i] = src[i];
    }
    // register-resident W tail: (i,f) and (g,o) pairs for rows [SMEM_D,128)
    unsigned long long wif[RREM], wgo[RREM];
#pragma unroll
    for (int r = 0; r < RREM; r++) {
        const unsigned long long* p =
            (const unsigned long long*)&g_Wp[(SMEM_D + r) * G4 + d * 4];
        wif[r] = p[0]; wgo[r] = p[1];
    }

    // zero h buffer 0 (buffer 1 is fully written during step 0 before use)
    for (int i = tid; i < HID * 8; i += 256) sh2[i] = 0.f;

    float cv0 = 0.f, cv1 = 0.f, e0 = 0.f, e1 = 0.f;

    // software pipeline for ihc4 prefetch
    unsigned long long aif0, ago0, aif1, ago1;
    int nn0, nn1;
    {
        int n0 = g_orders[(base + b0) * NN];
        int n1 = g_orders[(base + b1) * NN];
        ulonglong2 v0 = *(const ulonglong2*)&g_ihc4[n0 * G4 + d * 4];
        ulonglong2 v1 = *(const ulonglong2*)&g_ihc4[n1 * G4 + d * 4];
        aif0 = v0.x; ago0 = v0.y; aif1 = v1.x; ago1 = v1.y;
        nn0 = g_orders[(base + b0) * NN + 1];
        nn1 = g_orders[(base + b1) * NN + 1];
    }
    __syncthreads();

    int buf = 0;
    for (int t = 0; t < NN; t++) {
        // prefetch next step's ihc + node ids (hide under GEMV)
        ulonglong2 t0 = make_ulonglong2(0, 0), t1 = make_ulonglong2(0, 0);
        if (t + 1 < NN) {
            t0 = *(const ulonglong2*)&g_ihc4[nn0 * G4 + d * 4];
            t1 = *(const ulonglong2*)&g_ihc4[nn1 * G4 + d * 4];
        }
        if (t + 2 < NN) {
            nn0 = g_orders[(base + b0) * NN + t + 2];
            nn1 = g_orders[(base + b1) * NN + t + 2];
        }

        const float* shb = sh2 + buf * (HID * 8);
        // ---- GEMV over d' ----
#pragma unroll 8
        for (int dp = 0; dp < SMEM_D; dp++) {
            ulonglong2 w = *(const ulonglong2*)&sWp[dp * G4 + d * 4];
            ulonglong2 h = *(const ulonglong2*)&shb[dp * 8 + bg * 4];
            FFMA2(aif0, h.x, w.x);
            FFMA2(ago0, h.x, w.y);
            FFMA2(aif1, h.y, w.x);
            FFMA2(ago1, h.y, w.y);
        }
#pragma unroll
        for (int r = 0; r < RREM; r++) {
            ulonglong2 h =
                *(const ulonglong2*)&shb[(SMEM_D + r) * 8 + bg * 4];
            FFMA2(aif0, h.x, wif[r]);
            FFMA2(ago0, h.x, wgo[r]);
            FFMA2(aif1, h.y, wif[r]);
            FFMA2(ago1, h.y, wgo[r]);
        }

        // ---- activations on OWN accs (no cross-thread exchange) ----
        float2 if0 = *(float2*)&aif0, go0 = *(float2*)&ago0;
        float2 if1 = *(float2*)&aif1, go1 = *(float2*)&ago1;
        cv0 = fsig(if0.y) * cv0 + fsig(if0.x) * ftanh(go0.x);
        float h0 = fsig(go0.y) * ftanh(cv0);
        e0 += h0;
        cv1 = fsig(if1.y) * cv1 + fsig(if1.x) * ftanh(go1.x);
        float h1 = fsig(go1.y) * ftanh(cv1);
        e1 += h1;

        // write dup quad to the OTHER buffer (no race with concurrent readers)
        float* shn = sh2 + (buf ^ 1) * (HID * 8);
        *(float4*)&shn[d * 8 + bg * 4] = make_float4(h0, h0, h1, h1);

        // rotate pipeline
        aif0 = t0.x; ago0 = t0.y; aif1 = t1.x; ago1 = t1.y;
        __syncthreads();  // the only barrier per step
        buf ^= 1;
    }
    g_embed[(base + b0) * HID + d] = e0 * (1.0f / 512.0f);
    g_embed[(base + b1) * HID + d] = e1 * (1.0f / 512.0f);
}

// ---------------- Kernel F: 4-head MLP -> logits ----------------
__global__ void k_mlp(const float* __restrict__ W1s,
                      const float* __restrict__ b1s,
                      const float* __restrict__ W2s,
                      const float* __restrict__ b2s) {
    int n = blockIdx.x;
    int h = threadIdx.x;  // 128
    __shared__ float se[HID];
    __shared__ float red[128];
    se[h] = g_embed[n * HID + h];
    __syncthreads();
    for (int k = 0; k < 4; k++) {
        const float* W1 = W1s + k * HID * HID;
        float acc = b1s[k * HID + h];
#pragma unroll 8
        for (int d = 0; d < HID; d++) acc += se[d] * W1[d * HID + h];
        float r = fmaxf(acc, 0.f) * W2s[k * HID + h];
        red[h] = r;
        __syncthreads();
        for (int off = 64; off > 0; off >>= 1) {
            if (h < off) red[h] += red[h + off];
            __syncthreads();
        }
        if (h == 0) g_logits[k * NN + n] = red[0] + b2s[k];
        __syncthreads();
    }
}

// ---------------- Kernel G: loss + ensemble output ----------------
__global__ void k_final(const int* __restrict__ label,
                        const float* __restrict__ var_raw,
                        float* __restrict__ out) {
    int n = threadIdx.x;  // 512
    __shared__ float cw[4];
    __shared__ float red[NN];
    if (n < 4) {
        float x = var_raw[n];
        cw[n] = (x > 0.f) ? (x + log1pf(expf(-x))) : log1pf(expf(x));
    }
    __syncthreads();
    if (n == 0) {
        float s = cw[0] + cw[1] + cw[2] + cw[3];
        cw[0] /= s; cw[1] /= s; cw[2] /= s; cw[3] /= s;
    }
    __syncthreads();
    float lab = (float)label[0];
    float y = 0.f, lsum = 0.f;
#pragma unroll
    for (int k = 0; k < 4; k++) {
        float L = g_logits[k * NN + n];
        float ls_pos = (L > 0.f) ? -log1pf(expf(-L)) : (L - log1pf(expf(L)));
        float ls_neg = (L < 0.f) ? -log1pf(expf(L)) : (-L - log1pf(expf(-L)));
        lsum += -(lab * ls_pos + (1.f - lab) * ls_neg);
        y += cw[k] * sigf(L);
    }
    red[n] = lsum;
    __syncthreads();
    for (int off = 256; off > 0; off >>= 1) {
        if (n < off) red[n] += red[n + off];
        __syncthreads();
    }
    if (n == 0) out[0] = red[0] * (1.0f / 512.0f);  // sum_k mean_n
    out[1 + n] = y;
}

// ---------------- launcher ----------------
extern "C" void kernel_launch(void* const* d_in, const int* in_sizes, int n_in,
                              void* d_out, int out_size) {
    const int*   tags    = (const int*)d_in[0];
    const float* adj     = (const float*)d_in[1];
    const int*   label   = (const int*)d_in[2];
    const float* W_emb   = (const float*)d_in[3];
    const float* b_emb   = (const float*)d_in[4];
    const float* W_ih    = (const float*)d_in[5];
    const float* W_hh    = (const float*)d_in[6];
    const float* b_ih    = (const float*)d_in[7];
    const float* b_hh    = (const float*)d_in[8];
    const float* W1s     = (const float*)d_in[9];
    const float* b1s     = (const float*)d_in[10];
    const float* W2s     = (const float*)d_in[11];
    const float* b2s     = (const float*)d_in[12];
    const float* var_raw = (const float*)d_in[13];
    float* out = (float*)d_out;

    cudaFuncSetAttribute(k_lstm, cudaFuncAttributeMaxDynamicSharedMemorySize,
                         LSTM_SMEM_BYTES);

    // order keeps k_lstm as the 4th launch (ncu's sampled slot)
    k_embed<<<NN, 64>>>(tags, adj, W_emb, b_emb, W_hh);
    k_ihc<<<NN, G4>>>(W_ih, b_ih, b_hh);
    k_orders<<<NN, 256>>>(adj);
    k_lstm<<<NN / 4, 256, LSTM_SMEM_BYTES>>>();
    k_mlp<<<NN, 128>>>(W1s, b1s, W2s, b2s);
    k_final<<<1, NN>>>(label, var_raw, out);
    (void)in_sizes; (void)n_in; (void)out_size;
}

// round 12
// speedup vs baseline: 1.6053x; 1.6053x over previous
#include <cuda_runtime.h>
#include <math.h>
#include <stdint.h>

#define NN 512
#define EMB 64
#define HID 128
#define G4 512   // 4*HID
#define IN2 128  // 2*EMB

#define SMEM_D 48           // W rows (d') resident in SMEM (must be even)
#define SMEM_M (SMEM_D / 2) // 24 m-pairs in smem
#define RREM_M (64 - SMEM_M) // 40 m-pairs in registers (160 regs)
// dynamic smem floats: sW2 + double-buffered h [2][64][8] + sg [4][512]
#define LSTM_SMEM_FLOATS (SMEM_D * G4 + 2 * 64 * 8 + 4 * G4)
#define LSTM_SMEM_BYTES (LSTM_SMEM_FLOATS * 4)

// ---- scratch (device globals; no allocations allowed) ----
__device__ float g_input_feat[NN * IN2];   // [node][128]
__device__ float g_ihc[NN * G4];           // x@W_ih^T + b_ih + b_hh per node
__device__ int   g_orders[NN * NN];        // [start][step]
__device__ float g_Wp2[HID * G4];          // [m][j][2]: (W^T[2m][j], W^T[2m+1][j])
__device__ float g_embed[NN * HID];        // mean LSTM output per sequence
__device__ float g_logits[4 * NN];

// packed fp32x2 FMA (Blackwell): acc = a*b + acc, lanewise IEEE fp32
#define FFMA2(acc, a, b) \
    asm("fma.rn.f32x2 %0, %1, %2, %0;" : "+l"(acc) : "l"(a), "l"(b))

__device__ __forceinline__ unsigned long long pk2(float lo, float hi) {
    float2 f = make_float2(lo, hi);
    return *(unsigned long long*)&f;
}

// ---------------- Threefry2x32 (JAX-compatible) ----------------
__device__ __forceinline__ uint32_t rotl32(uint32_t x, int d) {
    return (x << d) | (x >> (32 - d));
}

__device__ __forceinline__ void threefry(uint32_t k0, uint32_t k1,
                                         uint32_t& x0, uint32_t& x1) {
    uint32_t ks2 = k0 ^ k1 ^ 0x1BD11BDAu;
    x0 += k0; x1 += k1;
    x0 += x1; x1 = rotl32(x1, 13); x1 ^= x0;
    x0 += x1; x1 = rotl32(x1, 15); x1 ^= x0;
    x0 += x1; x1 = rotl32(x1, 26); x1 ^= x0;
    x0 += x1; x1 = rotl32(x1, 6);  x1 ^= x0;
    x0 += k1; x1 += ks2 + 1u;
    x0 += x1; x1 = rotl32(x1, 17); x1 ^= x0;
    x0 += x1; x1 = rotl32(x1, 29); x1 ^= x0;
    x0 += x1; x1 = rotl32(x1, 16); x1 ^= x0;
    x0 += x1; x1 = rotl32(x1, 24); x1 ^= x0;
    x0 += ks2; x1 += k0 + 2u;
    x0 += x1; x1 = rotl32(x1, 13); x1 ^= x0;
    x0 += x1; x1 = rotl32(x1, 15); x1 ^= x0;
    x0 += x1; x1 = rotl32(x1, 26); x1 ^= x0;
    x0 += x1; x1 = rotl32(x1, 6);  x1 ^= x0;
    x0 += k0; x1 += k1 + 3u;
    x0 += x1; x1 = rotl32(x1, 17); x1 ^= x0;
    x0 += x1; x1 = rotl32(x1, 29); x1 ^= x0;
    x0 += x1; x1 = rotl32(x1, 16); x1 ^= x0;
    x0 += x1; x1 = rotl32(x1, 24); x1 ^= x0;
    x0 += k1; x1 += ks2 + 4u;
    x0 += x1; x1 = rotl32(x1, 13); x1 ^= x0;
    x0 += x1; x1 = rotl32(x1, 15); x1 ^= x0;
    x0 += x1; x1 = rotl32(x1, 26); x1 ^= x0;
    x0 += x1; x1 = rotl32(x1, 6);  x1 ^= x0;
    x0 += ks2; x1 += k0 + 5u;
}

// fast activations (err ~1e-6; recurrence is contractive)
__device__ __forceinline__ float fsig(float x) {
    return __fdividef(1.0f, 1.0f + __expf(-x));
}
__device__ __forceinline__ float ftanh(float x) {
    return __fdividef(2.0f, 1.0f + __expf(-2.0f * x)) - 1.0f;
}
__device__ __forceinline__ float sigf(float x) {  // accurate (non-LSTM paths)
    return 1.0f / (1.0f + expf(-x));
}

// ---------------- Kernel A: node_feat / neigh_feat + W repack --------------
__global__ void k_embed(const int* __restrict__ tags,
                        const float* __restrict__ adj,
                        const float* __restrict__ W_emb,
                        const float* __restrict__ b_emb,
                        const float* __restrict__ W_hh) {
    int i = blockIdx.x;
    int dd = threadIdx.x;  // 64
    __shared__ int stags[NN];
    for (int j = dd; j < NN; j += 64) stags[j] = tags[j];
    __syncthreads();
    float nf = W_emb[stags[i] * EMB + dd] + b_emb[dd];
    float acc = 0.f;
    const float* arow = adj + (size_t)i * NN;
    for (int j = 0; j < NN; j++) {
        if (arow[j] > 0.5f) acc += W_emb[stags[j] * EMB + dd];
    }
    g_input_feat[i * IN2 + dd] = nf;
    g_input_feat[i * IN2 + EMB + dd] = acc + b_emb[dd];

    // fused W repack: g_Wp2[m*1024 + j*2 + e] = W_hh[j*128 + 2m + e]
    int E0 = (i * 64 + dd) * 2;
#pragma unroll
    for (int c = 0; c < 2; c++) {
        int E = E0 + c;
        int m = E >> 10;
        int rem = E & 1023;
        int j = rem >> 1;
        int e = rem & 1;
        g_Wp2[E] = W_hh[j * 128 + 2 * m + e];
    }
}

// ---------------- Kernel C: per-node input-gate contribution ----------------
__global__ void k_ihc(const float* __restrict__ W_ih,
                      const float* __restrict__ b_ih,
                      const float* __restrict__ b_hh) {
    int node = blockIdx.x;
    int j = threadIdx.x;  // 512
    __shared__ float sx[IN2];
    if (j < IN2) sx[j] = g_input_feat[node * IN2 + j];
    __syncthreads();
    const float* wr = W_ih + j * IN2;
    float acc = 0.f;
#pragma unroll 8
    for (int d = 0; d < IN2; d++) acc += sx[d] * wr[d];
    g_ihc[node * G4 + j] = acc + b_ih[j] + b_hh[j];
}

// ---------------- Kernel D: greedy noisy random-walk orderings ----------------
// EXACTLY the measured-best (582us) R9 version: partitionable threefry
// (bit-exact) + exact candidate filter (noise in [0.01,0.1) => only i with
// adj[cur,i] >= max-0.09001 can win; gap >= 1e-5 >> fp32 rounding).
__device__ __forceinline__ float walk_noise1(uint32_t f1, uint32_t f2, int i) {
    const float scale = 0.1f - 0.01f;
    uint32_t a = 0u, b = (uint32_t)i;
    threefry(f1, f2, a, b);
    uint32_t bits = a ^ b;
    float u = __uint_as_float((bits >> 9) | 0x3f800000u) - 1.0f;
    return fmaxf(0.01f, __fadd_rn(__fmul_rn(u, scale), 0.01f));
}

__global__ void __launch_bounds__(256) k_orders(const float* __restrict__ adj) {
    int s = blockIdx.x;
    int tid = threadIdx.x;  // 256
    int lane = tid & 31, warp = tid >> 5;
    __shared__ uint32_t fi1[NN], fi2[NN];
    __shared__ unsigned char smask[NN];
    __shared__ float wmax[8];
    __shared__ unsigned long long wred[8];
    __shared__ short slist[NN];
    __shared__ int scnt;
    __shared__ int scur;

    uint32_t k1 = 0u, k2 = (uint32_t)s;
    threefry(0u, 42u, k1, k2);  // split(key(42), 512)[s]
#pragma unroll
    for (int c = 0; c < 2; c++) {
        int t = tid + c * 256;
        uint32_t f1 = 0u, f2 = (uint32_t)t;
        threefry(k1, k2, f1, f2);
        fi1[t] = f1; fi2[t] = f2;
    }
    smask[tid] = 1; smask[tid + 256] = 1;
    if (tid == 0) scnt = 0;
    __syncthreads();
    if (tid == 0) { smask[s] = 0; scur = s; g_orders[s * NN] = s; }
    __syncthreads();

    for (int t = 0; t < NN - 1; t++) {
        int cur = scur;
        const float* arow = adj + (size_t)cur * NN;
        float a0 = arow[tid], a1 = arow[tid + 256];
        bool m0 = smask[tid] != 0, m1 = smask[tid + 256] != 0;

        // phase A: masked max of adj row (no ciphers)
        float mx = fmaxf(m0 ? a0 : -1e30f, m1 ? a1 : -1e30f);
#pragma unroll
        for (int off = 16; off > 0; off >>= 1)
            mx = fmaxf(mx, __shfl_xor_sync(0xffffffffu, mx, off));
        if (lane == 0) wmax[warp] = mx;
        __syncthreads();
        float thr = wmax[0];
#pragma unroll
        for (int w = 1; w < 8; w++) thr = fmaxf(thr, wmax[w]);
        float thr2 = thr - 0.09001f;

        // phase B: ballot-compact candidate indices
        bool c0 = m0 && (a0 >= thr2);
        bool c1 = m1 && (a1 >= thr2);
        unsigned bal0 = __ballot_sync(0xffffffffu, c0);
        unsigned bal1 = __ballot_sync(0xffffffffu, c1);
        int cnt = __popc(bal0) + __popc(bal1);
        int basee = 0;
        if (lane == 0 && cnt) basee = atomicAdd(&scnt, cnt);
        basee = __shfl_sync(0xffffffffu, basee, 0);
        unsigned lmask = (1u << lane) - 1u;
        if (c0) slist[basee + __popc(bal0 & lmask)] = (short)tid;
        if (c1) slist[basee + __popc(bal0) + __popc(bal1 & lmask)] =
            (short)(tid + 256);
        __syncthreads();
        int nc = scnt;

        // phase C: ciphers only for candidates
        uint32_t f1 = fi1[t], f2 = fi2[t];
        unsigned long long key = 0ull;
        if (tid < nc) {
            int i = slist[tid];
            float v = arow[i] + walk_noise1(f1, f2, i);
            key = (((unsigned long long)__float_as_uint(v)) << 32) |
                  (unsigned long long)(unsigned)(NN - 1 - i);
        }
        if (tid + 256 < nc) {
            int i = slist[tid + 256];
            float v = arow[i] + walk_noise1(f1, f2, i);
            unsigned long long kk =
                (((unsigned long long)__float_as_uint(v)) << 32) |
                (unsigned long long)(unsigned)(NN - 1 - i);
            if (kk > key) key = kk;
        }
#pragma unroll
        for (int off = 16; off > 0; off >>= 1) {
            unsigned long long o = __shfl_xor_sync(0xffffffffu, key, off);
            if (o > key) key = o;
        }
        if (lane == 0) wred[warp] = key;
        __syncthreads();
        if (tid == 0) {
            unsigned long long best = wred[0];
#pragma unroll
            for (int w = 1; w < 8; w++) if (wred[w] > best) best = wred[w];
            int nxt = (NN - 1) - (int)(unsigned)(best & 0xffffffffu);
            g_orders[s * NN + t + 1] = nxt;
            smask[nxt] = 0;
            scur = nxt;
            scnt = 0;
        }
        __syncthreads();
    }
}

// ---------------- Kernel E: LSTM — even/odd-partial FFMA2 --------------------
// Thread owns gate-columns (j0, j0+1) for 4 sequences. Accumulator for column
// j, seq b is a packed pair (partial over even d', partial over odd d').
// h stored UN-duplicated as [m][b][2] = (h_b[2m], h_b[2m+1]): one LDS.128
// broadcast serves 2 d' x 2 seqs (halves h wavefronts vs the dup scheme).
// W repacked [m][j][2]; rows [SMEM_D,128) live in registers (160 regs).
__global__ void __launch_bounds__(256) k_lstm() {
    extern __shared__ float smem[];
    float* sW2 = smem;                     // [SMEM_M][512][2]
    float* sh2 = smem + SMEM_D * G4;       // [2][64][8]: (h0e,h0o,h1e,h1o,h2e,..)
    float* sg  = sh2 + 2 * 64 * 8;         // [4][512] gates

    int bb = blockIdx.x;     // 0..127
    int tid = threadIdx.x;   // 0..255
    int base = bb * 4;
    int j0 = tid * 2;

    // stage SMEM W
    {
        const float4* src = (const float4*)g_Wp2;
        float4* dst = (float4*)sW2;
        for (int i = tid; i < SMEM_D * G4 / 4; i += 256) dst[i] = src[i];
    }
    // register-resident W tail: for m in [SMEM_M,64): (pair for col j0, pair for col j0+1)
    ulonglong2 wr[RREM_M];
#pragma unroll
    for (int r = 0; r < RREM_M; r++)
        wr[r] = *(const ulonglong2*)&g_Wp2[((SMEM_M + r) * 512 + j0) * 2];

    // zero h buffer 0
    for (int i = tid; i < 2 * 64 * 8; i += 256) sh2[i] = 0.f;

    int dA = tid & 127, bA = tid >> 7, bB = bA + 2;
    float cA = 0.f, cB = 0.f, eA = 0.f, eB = 0.f;

    // pipeline: ihcv holds ihc u64 (j0,j0+1) per seq for step t; tmp for t+1
    unsigned long long ihcv[4], tmp[4];
    int ndB[4];
    {
        int nd0[4];
#pragma unroll
        for (int b = 0; b < 4; b++) nd0[b] = g_orders[(base + b) * NN];
#pragma unroll
        for (int b = 0; b < 4; b++)
            ihcv[b] = *(const unsigned long long*)&g_ihc[nd0[b] * G4 + j0];
#pragma unroll
        for (int b = 0; b < 4; b++) ndB[b] = g_orders[(base + b) * NN + 1];
    }
    __syncthreads();

    int buf = 0;
    for (int t = 0; t < NN; t++) {
        // issue next-step prefetches FIRST (complete under the GEMV)
        if (t + 1 < NN) {
#pragma unroll
            for (int b = 0; b < 4; b++)
                tmp[b] = *(const unsigned long long*)&g_ihc[ndB[b] * G4 + j0];
        }
        if (t + 2 < NN) {
#pragma unroll
            for (int b = 0; b < 4; b++)
                ndB[b] = g_orders[(base + b) * NN + t + 2];
        }

        // init accs: lane0 = ihc (so gate = (ihc + evens) + odds), lane1 = 0
        unsigned long long a00, a01, a10, a11, a20, a21, a30, a31;
        {
            float2 v0 = *(float2*)&ihcv[0];
            float2 v1 = *(float2*)&ihcv[1];
            float2 v2 = *(float2*)&ihcv[2];
            float2 v3 = *(float2*)&ihcv[3];
            a00 = pk2(v0.x, 0.f); a01 = pk2(v0.y, 0.f);
            a10 = pk2(v1.x, 0.f); a11 = pk2(v1.y, 0.f);
            a20 = pk2(v2.x, 0.f); a21 = pk2(v2.y, 0.f);
            a30 = pk2(v3.x, 0.f); a31 = pk2(v3.y, 0.f);
        }

        const float* shb = sh2 + buf * (64 * 8);
        // ---- GEMV over m = d'-pairs ----
#pragma unroll 6
        for (int m = 0; m < SMEM_M; m++) {
            ulonglong2 w = *(const ulonglong2*)&sW2[(m * 512 + j0) * 2];
            ulonglong2 hA = *(const ulonglong2*)&shb[m * 8];      // h0,h1 pairs
            ulonglong2 hB = *(const ulonglong2*)&shb[m * 8 + 4];  // h2,h3 pairs
            FFMA2(a00, hA.x, w.x); FFMA2(a01, hA.x, w.y);
            FFMA2(a10, hA.y, w.x); FFMA2(a11, hA.y, w.y);
            FFMA2(a20, hB.x, w.x); FFMA2(a21, hB.x, w.y);
            FFMA2(a30, hB.y, w.x); FFMA2(a31, hB.y, w.y);
        }
#pragma unroll
        for (int r = 0; r < RREM_M; r++) {
            int m = SMEM_M + r;
            ulonglong2 hA = *(const ulonglong2*)&shb[m * 8];
            ulonglong2 hB = *(const ulonglong2*)&shb[m * 8 + 4];
            FFMA2(a00, hA.x, wr[r].x); FFMA2(a01, hA.x, wr[r].y);
            FFMA2(a10, hA.y, wr[r].x); FFMA2(a11, hA.y, wr[r].y);
            FFMA2(a20, hB.x, wr[r].x); FFMA2(a21, hB.x, wr[r].y);
            FFMA2(a30, hB.y, wr[r].x); FFMA2(a31, hB.y, wr[r].y);
        }

        // combine even+odd lanes -> gates, write to sg
        {
            float2 c00 = *(float2*)&a00, c01 = *(float2*)&a01;
            float2 c10 = *(float2*)&a10, c11 = *(float2*)&a11;
            float2 c20 = *(float2*)&a20, c21 = *(float2*)&a21;
            float2 c30 = *(float2*)&a30, c31 = *(float2*)&a31;
            *(float2*)&sg[0 * G4 + j0] = make_float2(c00.x + c00.y, c01.x + c01.y);
            *(float2*)&sg[1 * G4 + j0] = make_float2(c10.x + c10.y, c11.x + c11.y);
            *(float2*)&sg[2 * G4 + j0] = make_float2(c20.x + c20.y, c21.x + c21.y);
            *(float2*)&sg[3 * G4 + j0] = make_float2(c30.x + c30.y, c31.x + c31.y);
        }
        __syncthreads();

        // ---- activations: this thread owns (bA,dA) and (bB,dA) ----
        float* shn = sh2 + (buf ^ 1) * (64 * 8);
        int hoff = (dA >> 1) * 8 + (dA & 1);
        {
            const float* sgb = sg + bA * G4;
            float gi = sgb[dA], gf = sgb[128 + dA];
            float gg = sgb[256 + dA], go = sgb[384 + dA];
            cA = fsig(gf) * cA + fsig(gi) * ftanh(gg);
            float h = fsig(go) * ftanh(cA);
            eA += h;
            shn[hoff + bA * 2] = h;
        }
        {
            const float* sgb = sg + bB * G4;
            float gi = sgb[dA], gf = sgb[128 + dA];
            float gg = sgb[256 + dA], go = sgb[384 + dA];
            cB = fsig(gf) * cB + fsig(gi) * ftanh(gg);
            float h = fsig(go) * ftanh(cB);
            eB += h;
            shn[hoff + bB * 2] = h;
        }
        // rotate pipeline
#pragma unroll
        for (int b = 0; b < 4; b++) ihcv[b] = tmp[b];
        __syncthreads();
        buf ^= 1;
    }
    g_embed[(base + bA) * HID + dA] = eA * (1.0f / 512.0f);
    g_embed[(base + bB) * HID + dA] = eB * (1.0f / 512.0f);
}

// ---------------- Kernel F: 4-head MLP -> logits ----------------
__global__ void k_mlp(const float* __restrict__ W1s,
                      const float* __restrict__ b1s,
                      const float* __restrict__ W2s,
                      const float* __restrict__ b2s) {
    int n = blockIdx.x;
    int h = threadIdx.x;  // 128
    __shared__ float se[HID];
    __shared__ float red[128];
    se[h] = g_embed[n * HID + h];
    __syncthreads();
    for (int k = 0; k < 4; k++) {
        const float* W1 = W1s + k * HID * HID;
        float acc = b1s[k * HID + h];
#pragma unroll 8
        for (int d = 0; d < HID; d++) acc += se[d] * W1[d * HID + h];
        float r = fmaxf(acc, 0.f) * W2s[k * HID + h];
        red[h] = r;
        __syncthreads();
        for (int off = 64; off > 0; off >>= 1) {
            if (h < off) red[h] += red[h + off];
            __syncthreads();
        }
        if (h == 0) g_logits[k * NN + n] = red[0] + b2s[k];
        __syncthreads();
    }
}

// ---------------- Kernel G: loss + ensemble output ----------------
__global__ void k_final(const int* __restrict__ label,
                        const float* __restrict__ var_raw,
                        float* __restrict__ out) {
    int n = threadIdx.x;  // 512
    __shared__ float cw[4];
    __shared__ float red[NN];
    if (n < 4) {
        float x = var_raw[n];
        cw[n] = (x > 0.f) ? (x + log1pf(expf(-x))) : log1pf(expf(x));
    }
    __syncthreads();
    if (n == 0) {
        float s = cw[0] + cw[1] + cw[2] + cw[3];
        cw[0] /= s; cw[1] /= s; cw[2] /= s; cw[3] /= s;
    }
    __syncthreads();
    float lab = (float)label[0];
    float y = 0.f, lsum = 0.f;
#pragma unroll
    for (int k = 0; k < 4; k++) {
        float L = g_logits[k * NN + n];
        float ls_pos = (L > 0.f) ? -log1pf(expf(-L)) : (L - log1pf(expf(L)));
        float ls_neg = (L < 0.f) ? -log1pf(expf(L)) : (-L - log1pf(expf(-L)));
        lsum += -(lab * ls_pos + (1.f - lab) * ls_neg);
        y += cw[k] * sigf(L);
    }
    red[n] = lsum;
    __syncthreads();
    for (int off = 256; off > 0; off >>= 1) {
        if (n < off) red[n] += red[n + off];
        __syncthreads();
    }
    if (n == 0) out[0] = red[0] * (1.0f / 512.0f);  // sum_k mean_n
    out[1 + n] = y;
}

// ---------------- launcher ----------------
extern "C" void kernel_launch(void* const* d_in, const int* in_sizes, int n_in,
                              void* d_out, int out_size) {
    const int*   tags    = (const int*)d_in[0];
    const float* adj     = (const float*)d_in[1];
    const int*   label   = (const int*)d_in[2];
    const float* W_emb   = (const float*)d_in[3];
    const float* b_emb   = (const float*)d_in[4];
    const float* W_ih    = (const float*)d_in[5];
    const float* W_hh    = (const float*)d_in[6];
    const float* b_ih    = (const float*)d_in[7];
    const float* b_hh    = (const float*)d_in[8];
    const float* W1s     = (const float*)d_in[9];
    const float* b1s     = (const float*)d_in[10];
    const float* W2s     = (const float*)d_in[11];
    const float* b2s     = (const float*)d_in[12];
    const float* var_raw = (const float*)d_in[13];
    float* out = (float*)d_out;

    cudaFuncSetAttribute(k_lstm, cudaFuncAttributeMaxDynamicSharedMemorySize,
                         LSTM_SMEM_BYTES);

    // order keeps k_lstm as the 4th launch (ncu's sampled slot)
    k_embed<<<NN, 64>>>(tags, adj, W_emb, b_emb, W_hh);
    k_ihc<<<NN, G4>>>(W_ih, b_ih, b_hh);
    k_orders<<<NN, 256>>>(adj);
    k_lstm<<<NN / 4, 256, LSTM_SMEM_BYTES>>>();
    k_mlp<<<NN, 128>>>(W1s, b1s, W2s, b2s);
    k_final<<<1, NN>>>(label, var_raw, out);
    (void)in_sizes; (void)n_in; (void)out_size;
}